// round 1
// baseline (speedup 1.0000x reference)
#include <cuda_runtime.h>
#include <cuda_bf16.h>

#define N_NODES 50000
#define N_EDGES 800000

// ---- scratch (allocation-free: __device__ globals) ----
__device__ float g_deg [N_NODES];
__device__ float g_dinv[N_NODES];
__device__ float g_norm[N_EDGES];
__device__ float g_t [N_NODES * 64];
__device__ float g_h1[N_NODES * 64];
__device__ float g_h2[N_NODES * 64];

// ---------------------------------------------------------------------------
__global__ void zero_deg_kernel() {
    int n = blockIdx.x * blockDim.x + threadIdx.x;
    if (n < N_NODES) g_deg[n] = 0.0f;
}

__global__ void deg_kernel(const int* __restrict__ row) {
    int e = blockIdx.x * blockDim.x + threadIdx.x;
    if (e < N_EDGES) atomicAdd(&g_deg[row[e]], 1.0f);
}

__global__ void dinv_kernel() {
    int n = blockIdx.x * blockDim.x + threadIdx.x;
    if (n < N_NODES) {
        float d = g_deg[n];
        g_dinv[n] = (d > 0.0f) ? rsqrtf(d) : 0.0f;
    }
}

__global__ void norm_kernel(const int* __restrict__ row, const int* __restrict__ col) {
    int e = blockIdx.x * blockDim.x + threadIdx.x;
    if (e < N_EDGES) g_norm[e] = g_dinv[row[e]] * g_dinv[col[e]];
}

// ---------------------------------------------------------------------------
// C[N, HOUT] = (RELU_IN ? relu(A) : A)[N,64] @ W[64,HOUT] (+ bias)
// Block: 64 rows x HOUT cols, 4x4 register microtile per thread.
// blockDim.x = 16 * (HOUT/4).
template <int HOUT, bool RELU_IN>
__global__ void gemm_kernel(const float* __restrict__ A,
                            const float* __restrict__ W,
                            const float* __restrict__ bias,
                            float* __restrict__ C) {
    __shared__ float xs[64][65];       // padded: avoid bank conflicts on column reads
    __shared__ float ws[64 * HOUT];

    const int tid  = threadIdx.x;
    const int nth  = 16 * (HOUT / 4);
    const int row0 = blockIdx.x * 64;

    // load W tile (64 x HOUT) via float4
    for (int i = tid; i < 64 * HOUT / 4; i += nth)
        reinterpret_cast<float4*>(ws)[i] = reinterpret_cast<const float4*>(W)[i];

    // load A tile (64 rows x 64 cols) via float4, optional relu, zero-pad OOB rows
    for (int i = tid; i < 64 * 16; i += nth) {
        int r  = i >> 4;
        int c4 = i & 15;
        float4 v = make_float4(0.f, 0.f, 0.f, 0.f);
        int gr = row0 + r;
        if (gr < N_NODES) v = reinterpret_cast<const float4*>(A)[gr * 16 + c4];
        if (RELU_IN) {
            v.x = fmaxf(v.x, 0.f); v.y = fmaxf(v.y, 0.f);
            v.z = fmaxf(v.z, 0.f); v.w = fmaxf(v.w, 0.f);
        }
        xs[r][c4 * 4 + 0] = v.x; xs[r][c4 * 4 + 1] = v.y;
        xs[r][c4 * 4 + 2] = v.z; xs[r][c4 * 4 + 3] = v.w;
    }
    __syncthreads();

    const int tr = tid / (HOUT / 4);
    const int tc = tid % (HOUT / 4);
    const int r0 = tr * 4, c0 = tc * 4;

    float acc[4][4];
#pragma unroll
    for (int i = 0; i < 4; i++)
#pragma unroll
        for (int j = 0; j < 4; j++) acc[i][j] = 0.f;

#pragma unroll 16
    for (int k = 0; k < 64; k++) {
        float4 wv = *reinterpret_cast<const float4*>(&ws[k * HOUT + c0]);
        float xv0 = xs[r0 + 0][k];
        float xv1 = xs[r0 + 1][k];
        float xv2 = xs[r0 + 2][k];
        float xv3 = xs[r0 + 3][k];
        acc[0][0] += xv0 * wv.x; acc[0][1] += xv0 * wv.y; acc[0][2] += xv0 * wv.z; acc[0][3] += xv0 * wv.w;
        acc[1][0] += xv1 * wv.x; acc[1][1] += xv1 * wv.y; acc[1][2] += xv1 * wv.z; acc[1][3] += xv1 * wv.w;
        acc[2][0] += xv2 * wv.x; acc[2][1] += xv2 * wv.y; acc[2][2] += xv2 * wv.z; acc[2][3] += xv2 * wv.w;
        acc[3][0] += xv3 * wv.x; acc[3][1] += xv3 * wv.y; acc[3][2] += xv3 * wv.z; acc[3][3] += xv3 * wv.w;
    }

    float4 bv = make_float4(0.f, 0.f, 0.f, 0.f);
    if (bias) bv = *reinterpret_cast<const float4*>(bias + c0);

#pragma unroll
    for (int i = 0; i < 4; i++) {
        int gr = row0 + r0 + i;
        if (gr < N_NODES) {
            float4 o;
            o.x = acc[i][0] + bv.x; o.y = acc[i][1] + bv.y;
            o.z = acc[i][2] + bv.z; o.w = acc[i][3] + bv.w;
            *reinterpret_cast<float4*>(C + gr * HOUT + c0) = o;
        }
    }
}

// ---------------------------------------------------------------------------
// h[col[e]] += t[row[e]] * norm[e]   (64 floats per edge, float4-vectorized
// gather + sm_90+ vectorized red.global.add.v4.f32 scatter)
__global__ void scatter_kernel(const float* __restrict__ t,
                               const int* __restrict__ row,
                               const int* __restrict__ col,
                               float* __restrict__ h) {
    unsigned gid = blockIdx.x * blockDim.x + threadIdx.x;
    unsigned e = gid >> 4;              // 16 float4 chunks per edge
    if (e >= N_EDGES) return;
    int c  = (gid & 15) << 2;
    int r  = row[e];                    // broadcast within half-warp group
    int cl = col[e];
    float nv = g_norm[e];
    float4 v = *reinterpret_cast<const float4*>(t + r * 64 + c);
    float* dst = h + cl * 64 + c;
    asm volatile("red.global.add.v4.f32 [%0], {%1, %2, %3, %4};"
                 :: "l"(dst), "f"(v.x * nv), "f"(v.y * nv),
                    "f"(v.z * nv), "f"(v.w * nv)
                 : "memory");
}

// ---------------------------------------------------------------------------
extern "C" void kernel_launch(void* const* d_in, const int* in_sizes, int n_in,
                              void* d_out, int out_size) {
    const float* x      = (const float*)d_in[0];
    const int*   ei     = (const int*)d_in[1];
    const int*   row    = ei;
    const int*   col    = ei + N_EDGES;
    const float* W_in1  = (const float*)d_in[2];
    const float* W_nb1  = (const float*)d_in[3];
    const float* b1     = (const float*)d_in[4];
    const float* W_in2  = (const float*)d_in[5];
    const float* W_nb2  = (const float*)d_in[6];
    const float* b2     = (const float*)d_in[7];
    const float* W_out  = (const float*)d_in[8];
    const float* b_out  = (const float*)d_in[9];
    float*       out    = (float*)d_out;

    float *t_p, *h1_p, *h2_p;
    cudaGetSymbolAddress((void**)&t_p,  g_t);
    cudaGetSymbolAddress((void**)&h1_p, g_h1);
    cudaGetSymbolAddress((void**)&h2_p, g_h2);

    const int TB = 256;
    const int node_blocks = (N_NODES + TB - 1) / TB;
    const int edge_blocks = (N_EDGES + TB - 1) / TB;
    const int gemm_blocks = (N_NODES + 63) / 64;
    const int scat_blocks = (N_EDGES * 16 + TB - 1) / TB;

    // degree -> dinv -> per-edge norm
    zero_deg_kernel<<<node_blocks, TB>>>();
    deg_kernel<<<edge_blocks, TB>>>(row);
    dinv_kernel<<<node_blocks, TB>>>();
    norm_kernel<<<edge_blocks, TB>>>(row, col);

    // layer 1
    gemm_kernel<64, false><<<gemm_blocks, 256>>>(x, W_nb1, nullptr, t_p);
    gemm_kernel<64, false><<<gemm_blocks, 256>>>(x, W_in1, b1, h1_p);
    scatter_kernel<<<scat_blocks, TB>>>(t_p, row, col, h1_p);

    // layer 2 (relu fused into GEMM input loads)
    gemm_kernel<64, true><<<gemm_blocks, 256>>>(h1_p, W_nb2, nullptr, t_p);
    gemm_kernel<64, true><<<gemm_blocks, 256>>>(h1_p, W_in2, b2, h2_p);
    scatter_kernel<<<scat_blocks, TB>>>(t_p, row, col, h2_p);

    // output projection (relu fused)
    gemm_kernel<32, true><<<gemm_blocks, 128>>>(h2_p, W_out, b_out, out);
}